// round 7
// baseline (speedup 1.0000x reference)
#include <cuda_runtime.h>

#define NPTS   100000
#define BATCH  4096
#define KSEL   10
#define TPB    128
#define RPB    4       // rays per block
#define SUBS   32      // lanes per ray
#define GRID   (BATCH / RPB)   // 1024 blocks
#define UNR    8
#define NCHUNK (NPTS / (SUBS * UNR))   // 390; tail = 160 points (5 per lane)

__device__ float4 g_packed[NPTS];   // (-2x, -2y, -2z, |x|^2)

__global__ __launch_bounds__(256)
void pack_kernel(const float* __restrict__ xyz)
{
    int i = blockIdx.x * 256 + threadIdx.x;
    if (i < NPTS) {
        float x = xyz[i * 3 + 0];
        float y = xyz[i * 3 + 1];
        float z = xyz[i * 3 + 2];
        float q = fmaf(x, x, fmaf(y, y, z * z));
        g_packed[i] = make_float4(-2.0f * x, -2.0f * y, -2.0f * z, q);
    }
}

__global__ __launch_bounds__(TPB)       // no min-blocks: do NOT cap regs (R4's spill bug)
void gs_topk_kernel(const float* __restrict__ rays_o,
                    const float* __restrict__ rays_d,
                    const float* __restrict__ fdc,
                    const float* __restrict__ opac,
                    float* __restrict__ out)
{
    __shared__ float md2 [RPB * SUBS * KSEL];
    __shared__ int   midx[RPB * SUBS * KSEL];
    __shared__ float sT[RPB];
    volatile float* sTv = sT;

    const int t       = threadIdx.x;
    const int rl      = t & (RPB - 1);
    const int sub     = t >> 2;                 // 0..31
    const int rayBase = blockIdx.x * RPB;

    float cx, cy, cz, C;
    {
        int r = rayBase + rl;
        cx = fmaf(3.0f, rays_d[r * 3 + 0], rays_o[r * 3 + 0]);
        cy = fmaf(3.0f, rays_d[r * 3 + 1], rays_o[r * 3 + 1]);
        cz = fmaf(3.0f, rays_d[r * 3 + 2], rays_o[r * 3 + 2]);
        C  = cx * cx + cy * cy + cz * cz;
    }
    if (t < RPB) sT[t] = 3.0e38f;
    __syncthreads();

    // Per-lane sorted (ascending) top-K in s-domain (s = d^2 - C)
    float best[KSEL];
    int   bidx[KSEL];
#pragma unroll
    for (int j = 0; j < KSEL; j++) { best[j] = 3.0e38f; bidx[j] = 0; }
    float tloc = 3.0e38f;

    const float4* p = g_packed + sub;
    int pbase = sub;

#pragma unroll 1
    for (int c = 0; c < NCHUNK; c++) {
        float Tl = fminf(sTv[rl], tloc);
        float s[UNR];
#pragma unroll
        for (int u = 0; u < UNR; u++) {
            float4 q = p[u * SUBS];
            s[u] = fmaf(cx, q.x, fmaf(cy, q.y, fmaf(cz, q.z, q.w)));
        }
        float m01 = fminf(s[0], s[1]), m23 = fminf(s[2], s[3]);
        float m45 = fminf(s[4], s[5]), m67 = fminf(s[6], s[7]);
        float m = fminf(fminf(m01, m23), fminf(m45, m67));
        if (m < Tl) {
#pragma unroll
            for (int u = 0; u < UNR; u++) {
                if (s[u] < tloc) {
                    float v  = s[u];
                    int   ii = pbase + u * SUBS;
#pragma unroll
                    for (int j = 0; j < KSEL; j++) {
                        if (v < best[j]) {
                            float tv = best[j]; int ti = bidx[j];
                            best[j] = v; bidx[j] = ii;
                            v = tv; ii = ti;
                        }
                    }
                    tloc = best[KSEL - 1];
                }
            }
            if (tloc < sTv[rl]) sTv[rl] = tloc;   // benign race: any stored value is a valid bound
        }
        p     += UNR * SUBS;
        pbase += UNR * SUBS;
    }
    // Tail: 5 points per lane (99840..99999)
#pragma unroll 1
    for (int k = NCHUNK * UNR * SUBS + sub; k < NPTS; k += SUBS) {
        float4 q = g_packed[k];
        float  s = fmaf(cx, q.x, fmaf(cy, q.y, fmaf(cz, q.z, q.w)));
        if (s < tloc) {
            float v = s; int ii = k;
#pragma unroll
            for (int j = 0; j < KSEL; j++) {
                if (v < best[j]) {
                    float tv = best[j]; int ti = bidx[j];
                    best[j] = v; bidx[j] = ii;
                    v = tv; ii = ti;
                }
            }
            tloc = best[KSEL - 1];
        }
    }

    const int lbase = (rl * SUBS + sub) * KSEL;
#pragma unroll
    for (int j = 0; j < KSEL; j++) {
        md2[lbase + j]  = best[j] + C;            // back to d^2 domain
        midx[lbase + j] = bidx[j];
    }

    // Parallel pairwise merge: 32 sorted lists -> 1 per ray
    for (int stride = SUBS / 2; stride >= 1; stride >>= 1) {
        __syncthreads();
        if (sub < stride) {
            int a = (rl * SUBS + sub) * KSEL;
            int b = (rl * SUBS + sub + stride) * KSEL;
            float ov[KSEL]; int oi[KSEL];
            int ia = 0, ib = 0;
#pragma unroll
            for (int k = 0; k < KSEL; k++) {
                float va = md2[a + ia], vb = md2[b + ib];
                if (va <= vb) { ov[k] = va; oi[k] = midx[a + ia]; ia++; }
                else          { ov[k] = vb; oi[k] = midx[b + ib]; ib++; }
            }
#pragma unroll
            for (int k = 0; k < KSEL; k++) { md2[a + k] = ov[k]; midx[a + k] = oi[k]; }
        }
    }
    __syncthreads();

    // Epilogue: one thread per ray
    if (t < RPB) {
        int a = (t * SUBS) * KSEL;
        float wsum = 0.f, r0 = 0.f, g0 = 0.f, b0 = 0.f;
#pragma unroll
        for (int k = 0; k < KSEL; k++) {
            float d2 = md2[a + k];
            int   ii = midx[a + k];
            float d  = sqrtf(fmaxf(d2, 0.0f));
            float op = 1.0f / (1.0f + expf(-opac[ii]));
            float w  = expf(-0.1f * d) * op;
            wsum += w;
            float c0 = 1.0f / (1.0f + expf(-fdc[ii * 3 + 0]));
            float c1 = 1.0f / (1.0f + expf(-fdc[ii * 3 + 1]));
            float c2 = 1.0f / (1.0f + expf(-fdc[ii * 3 + 2]));
            r0 = fmaf(w, c0, r0);
            g0 = fmaf(w, c1, g0);
            b0 = fmaf(w, c2, b0);
        }
        float inv = 1.0f / (wsum + 1e-8f);
        int ray = rayBase + t;
        out[ray * 3 + 0] = r0 * inv;
        out[ray * 3 + 1] = g0 * inv;
        out[ray * 3 + 2] = b0 * inv;
    }
}

extern "C" void kernel_launch(void* const* d_in, const int* in_sizes, int n_in,
                              void* d_out, int out_size)
{
    const float* rays_o = (const float*)d_in[0];
    const float* rays_d = (const float*)d_in[1];
    const float* xyz    = (const float*)d_in[2];
    const float* fdc    = (const float*)d_in[3];
    const float* opac   = (const float*)d_in[4];
    float* out = (float*)d_out;

    pack_kernel<<<(NPTS + 255) / 256, 256>>>(xyz);
    gs_topk_kernel<<<GRID, TPB>>>(rays_o, rays_d, fdc, opac, out);
}

// round 8
// speedup vs baseline: 1.1466x; 1.1466x over previous
#include <cuda_runtime.h>

#define NPTS   100000
#define BATCH  4096
#define KSEL   10
#define TPB    128
#define RPB    8                       // rays per block (2 per warp)
#define PSPLIT 2
#define SLICE  (NPTS / PSPLIT)         // 50000
#define GRID   ((BATCH / RPB) * PSPLIT) // 1024
#define UNR    8
#define NCHUNK (SLICE / (32 * UNR))    // 195; tail = 80 points

__device__ float4 g_packed[NPTS];                  // (-2x, -2y, -2z, |x|^2)
__device__ float  g_pd2 [PSPLIT * BATCH * KSEL];   // partial top-K d^2
__device__ int    g_pidx[PSPLIT * BATCH * KSEL];   // partial top-K indices

__global__ __launch_bounds__(256)
void pack_kernel(const float* __restrict__ xyz)
{
    int i = blockIdx.x * 256 + threadIdx.x;
    if (i < NPTS) {
        float x = xyz[i * 3 + 0];
        float y = xyz[i * 3 + 1];
        float z = xyz[i * 3 + 2];
        float q = fmaf(x, x, fmaf(y, y, z * z));
        g_packed[i] = make_float4(-2.0f * x, -2.0f * y, -2.0f * z, q);
    }
}

__global__ __launch_bounds__(TPB, 8)
void scan_kernel(const float* __restrict__ rays_o,
                 const float* __restrict__ rays_d)
{
    __shared__ float md2s [RPB * 32 * KSEL];   // 10 KB  (s-domain during scan)
    __shared__ int   midxs[RPB * 32 * KSEL];   // 10 KB
    __shared__ float sT[RPB];
    volatile float* sTv = sT;

    const int t     = threadIdx.x;
    const int lane  = t & 31;
    const int w     = t >> 5;              // warp 0..3
    const int slice = blockIdx.x & 1;
    const int rayBase = (blockIdx.x >> 1) * RPB;
    const int rA = 2 * w, rB = 2 * w + 1;  // local rays owned by this warp

    float ax, ay, az, CA, bx, by, bz, CB;
    {
        int gA = rayBase + rA, gB = rayBase + rB;
        ax = fmaf(3.0f, rays_d[gA * 3 + 0], rays_o[gA * 3 + 0]);
        ay = fmaf(3.0f, rays_d[gA * 3 + 1], rays_o[gA * 3 + 1]);
        az = fmaf(3.0f, rays_d[gA * 3 + 2], rays_o[gA * 3 + 2]);
        CA = ax * ax + ay * ay + az * az;
        bx = fmaf(3.0f, rays_d[gB * 3 + 0], rays_o[gB * 3 + 0]);
        by = fmaf(3.0f, rays_d[gB * 3 + 1], rays_o[gB * 3 + 1]);
        bz = fmaf(3.0f, rays_d[gB * 3 + 2], rays_o[gB * 3 + 2]);
        CB = bx * bx + by * by + bz * bz;
    }
    const int baseA = (rA * 32 + lane) * KSEL;
    const int baseB = (rB * 32 + lane) * KSEL;
#pragma unroll
    for (int j = 0; j < KSEL; j++) {
        md2s[baseA + j] = 3.0e38f; midxs[baseA + j] = 0;
        md2s[baseB + j] = 3.0e38f; midxs[baseB + j] = 0;
    }
    if (t < RPB) sT[t] = 3.0e38f;
    __syncthreads();

    float tlA = 3.0e38f, tlB = 3.0e38f;    // own 10th-best (s-domain)
    const int sliceLo = slice * SLICE;
    const float4* p = g_packed + sliceLo + lane;
    int pbase = sliceLo + lane;

#pragma unroll 1
    for (int c = 0; c < NCHUNK; c++) {
        float TA = fminf(sTv[rA], tlA);
        float TB = fminf(sTv[rB], tlB);
        float4 qs[UNR];
#pragma unroll
        for (int u = 0; u < UNR; u++) qs[u] = p[u * 32];

        float mA, mB;
        {
            float a0 = fmaf(ax, qs[0].x, fmaf(ay, qs[0].y, fmaf(az, qs[0].z, qs[0].w)));
            float a1 = fmaf(ax, qs[1].x, fmaf(ay, qs[1].y, fmaf(az, qs[1].z, qs[1].w)));
            float a2 = fmaf(ax, qs[2].x, fmaf(ay, qs[2].y, fmaf(az, qs[2].z, qs[2].w)));
            float a3 = fmaf(ax, qs[3].x, fmaf(ay, qs[3].y, fmaf(az, qs[3].z, qs[3].w)));
            float a4 = fmaf(ax, qs[4].x, fmaf(ay, qs[4].y, fmaf(az, qs[4].z, qs[4].w)));
            float a5 = fmaf(ax, qs[5].x, fmaf(ay, qs[5].y, fmaf(az, qs[5].z, qs[5].w)));
            float a6 = fmaf(ax, qs[6].x, fmaf(ay, qs[6].y, fmaf(az, qs[6].z, qs[6].w)));
            float a7 = fmaf(ax, qs[7].x, fmaf(ay, qs[7].y, fmaf(az, qs[7].z, qs[7].w)));
            mA = fminf(fminf(fminf(a0, a1), fminf(a2, a3)),
                       fminf(fminf(a4, a5), fminf(a6, a7)));
            float b0 = fmaf(bx, qs[0].x, fmaf(by, qs[0].y, fmaf(bz, qs[0].z, qs[0].w)));
            float b1 = fmaf(bx, qs[1].x, fmaf(by, qs[1].y, fmaf(bz, qs[1].z, qs[1].w)));
            float b2 = fmaf(bx, qs[2].x, fmaf(by, qs[2].y, fmaf(bz, qs[2].z, qs[2].w)));
            float b3 = fmaf(bx, qs[3].x, fmaf(by, qs[3].y, fmaf(bz, qs[3].z, qs[3].w)));
            float b4 = fmaf(bx, qs[4].x, fmaf(by, qs[4].y, fmaf(bz, qs[4].z, qs[4].w)));
            float b5 = fmaf(bx, qs[5].x, fmaf(by, qs[5].y, fmaf(bz, qs[5].z, qs[5].w)));
            float b6 = fmaf(bx, qs[6].x, fmaf(by, qs[6].y, fmaf(bz, qs[6].z, qs[6].w)));
            float b7 = fmaf(bx, qs[7].x, fmaf(by, qs[7].y, fmaf(bz, qs[7].z, qs[7].w)));
            mB = fminf(fminf(fminf(b0, b1), fminf(b2, b3)),
                       fminf(fminf(b4, b5), fminf(b6, b7)));
        }

        if (mA < TA || mB < TB) {
            if (mA < TA) {
#pragma unroll
                for (int u = 0; u < UNR; u++) {
                    float s = fmaf(ax, qs[u].x, fmaf(ay, qs[u].y, fmaf(az, qs[u].z, qs[u].w)));
                    if (s < tlA) {
                        int j = KSEL - 1;
                        while (j > 0 && md2s[baseA + j - 1] > s) {
                            md2s[baseA + j]  = md2s[baseA + j - 1];
                            midxs[baseA + j] = midxs[baseA + j - 1];
                            j--;
                        }
                        md2s[baseA + j]  = s;
                        midxs[baseA + j] = pbase + u * 32;
                        tlA = md2s[baseA + KSEL - 1];
                    }
                }
                if (tlA < sTv[rA]) sTv[rA] = tlA;   // benign race: any value is a valid bound
            }
            if (mB < TB) {
#pragma unroll
                for (int u = 0; u < UNR; u++) {
                    float s = fmaf(bx, qs[u].x, fmaf(by, qs[u].y, fmaf(bz, qs[u].z, qs[u].w)));
                    if (s < tlB) {
                        int j = KSEL - 1;
                        while (j > 0 && md2s[baseB + j - 1] > s) {
                            md2s[baseB + j]  = md2s[baseB + j - 1];
                            midxs[baseB + j] = midxs[baseB + j - 1];
                            j--;
                        }
                        md2s[baseB + j]  = s;
                        midxs[baseB + j] = pbase + u * 32;
                        tlB = md2s[baseB + KSEL - 1];
                    }
                }
                if (tlB < sTv[rB]) sTv[rB] = tlB;
            }
        }
        p     += UNR * 32;
        pbase += UNR * 32;
    }

    // Tail: 80 points of this slice
#pragma unroll 1
    for (int k = sliceLo + NCHUNK * UNR * 32 + lane; k < sliceLo + SLICE; k += 32) {
        float4 q = g_packed[k];
        float sA = fmaf(ax, q.x, fmaf(ay, q.y, fmaf(az, q.z, q.w)));
        float sB = fmaf(bx, q.x, fmaf(by, q.y, fmaf(bz, q.z, q.w)));
        if (sA < tlA) {
            int j = KSEL - 1;
            while (j > 0 && md2s[baseA + j - 1] > sA) {
                md2s[baseA + j] = md2s[baseA + j - 1]; midxs[baseA + j] = midxs[baseA + j - 1]; j--;
            }
            md2s[baseA + j] = sA; midxs[baseA + j] = k;
            tlA = md2s[baseA + KSEL - 1];
        }
        if (sB < tlB) {
            int j = KSEL - 1;
            while (j > 0 && md2s[baseB + j - 1] > sB) {
                md2s[baseB + j] = md2s[baseB + j - 1]; midxs[baseB + j] = midxs[baseB + j - 1]; j--;
            }
            md2s[baseB + j] = sB; midxs[baseB + j] = k;
            tlB = md2s[baseB + KSEL - 1];
        }
    }

    // Convert own lists to d^2 domain
#pragma unroll
    for (int j = 0; j < KSEL; j++) {
        md2s[baseA + j] += CA;
        md2s[baseB + j] += CB;
    }

    // Tree merge: 32 lists -> 1 per ray
    const int mray = t & 7;
    const int msub = t >> 3;
    for (int stride = 16; stride >= 1; stride >>= 1) {
        __syncthreads();
        if (msub < stride) {
            int a = (mray * 32 + msub) * KSEL;
            int b = (mray * 32 + msub + stride) * KSEL;
            float ov[KSEL]; int oi[KSEL];
            int ia = 0, ib = 0;
#pragma unroll
            for (int k = 0; k < KSEL; k++) {
                float va = md2s[a + ia], vb = md2s[b + ib];
                if (va <= vb) { ov[k] = va; oi[k] = midxs[a + ia]; ia++; }
                else          { ov[k] = vb; oi[k] = midxs[b + ib]; ib++; }
            }
#pragma unroll
            for (int k = 0; k < KSEL; k++) { md2s[a + k] = ov[k]; midxs[a + k] = oi[k]; }
        }
    }
    __syncthreads();

    if (t < RPB) {
        int src = (t * 32) * KSEL;
        int dst = (slice * BATCH + rayBase + t) * KSEL;
#pragma unroll
        for (int k = 0; k < KSEL; k++) {
            g_pd2 [dst + k] = md2s[src + k];
            g_pidx[dst + k] = midxs[src + k];
        }
    }
}

__global__ __launch_bounds__(128)
void finalize_kernel(const float* __restrict__ fdc,
                     const float* __restrict__ opac,
                     float* __restrict__ out)
{
    int ray = blockIdx.x * 128 + threadIdx.x;
    if (ray >= BATCH) return;
    int a = ray * KSEL, b = (BATCH + ray) * KSEL;
    int ia = 0, ib = 0;
    float wsum = 0.f, r0 = 0.f, g0 = 0.f, b0 = 0.f;
#pragma unroll
    for (int k = 0; k < KSEL; k++) {
        float va = (ia < KSEL) ? g_pd2[a + ia] : 3.0e38f;
        float vb = (ib < KSEL) ? g_pd2[b + ib] : 3.0e38f;
        float d2; int ii;
        if (va <= vb) { d2 = va; ii = g_pidx[a + ia]; ia++; }
        else          { d2 = vb; ii = g_pidx[b + ib]; ib++; }
        float d  = sqrtf(fmaxf(d2, 0.0f));
        float op = 1.0f / (1.0f + expf(-opac[ii]));
        float w  = expf(-0.1f * d) * op;
        wsum += w;
        float c0 = 1.0f / (1.0f + expf(-fdc[ii * 3 + 0]));
        float c1 = 1.0f / (1.0f + expf(-fdc[ii * 3 + 1]));
        float c2 = 1.0f / (1.0f + expf(-fdc[ii * 3 + 2]));
        r0 = fmaf(w, c0, r0);
        g0 = fmaf(w, c1, g0);
        b0 = fmaf(w, c2, b0);
    }
    float inv = 1.0f / (wsum + 1e-8f);
    out[ray * 3 + 0] = r0 * inv;
    out[ray * 3 + 1] = g0 * inv;
    out[ray * 3 + 2] = b0 * inv;
}

extern "C" void kernel_launch(void* const* d_in, const int* in_sizes, int n_in,
                              void* d_out, int out_size)
{
    const float* rays_o = (const float*)d_in[0];
    const float* rays_d = (const float*)d_in[1];
    const float* xyz    = (const float*)d_in[2];
    const float* fdc    = (const float*)d_in[3];
    const float* opac   = (const float*)d_in[4];
    float* out = (float*)d_out;

    pack_kernel<<<(NPTS + 255) / 256, 256>>>(xyz);
    scan_kernel<<<GRID, TPB>>>(rays_o, rays_d);
    finalize_kernel<<<BATCH / 128, 128>>>(fdc, opac, out);
}

// round 9
// speedup vs baseline: 2.0680x; 1.8036x over previous
#include <cuda_runtime.h>

#define NPTS   100000
#define BATCH  4096
#define KSEL   10
#define TPB    128
#define RPB    8                        // rays per block (8-way load broadcast)
#define NSUB   (TPB / RPB)              // 16 subs partition the points
#define PSPLIT 2
#define SLICE  (NPTS / PSPLIT)          // 50000
#define GRID   ((BATCH / RPB) * PSPLIT) // 1024 blocks
#define UNR    8
#define CHPTS  (NSUB * UNR)             // 128 points per chunk per block
#define NCHUNK (SLICE / CHPTS)          // 390; tail = 80 points (5 per sub)

__device__ float4 g_packed[NPTS];                  // (-2x, -2y, -2z, |x|^2)
__device__ float  g_pd2 [PSPLIT * BATCH * KSEL];
__device__ int    g_pidx[PSPLIT * BATCH * KSEL];

__global__ __launch_bounds__(256)
void pack_kernel(const float* __restrict__ xyz)
{
    int i = blockIdx.x * 256 + threadIdx.x;
    if (i < NPTS) {
        float x = xyz[i * 3 + 0];
        float y = xyz[i * 3 + 1];
        float z = xyz[i * 3 + 2];
        float q = fmaf(x, x, fmaf(y, y, z * z));
        g_packed[i] = make_float4(-2.0f * x, -2.0f * y, -2.0f * z, q);
    }
}

__global__ __launch_bounds__(TPB, 6)    // 85-reg budget: fits ~74-reg live set, no spills
void scan_kernel(const float* __restrict__ rays_o,
                 const float* __restrict__ rays_d)
{
    __shared__ float md2s [RPB * NSUB * KSEL];   // 5 KB
    __shared__ int   midxs[RPB * NSUB * KSEL];   // 5 KB
    __shared__ float sT[RPB];
    volatile float* sTv = sT;

    const int t       = threadIdx.x;
    const int rl      = t & (RPB - 1);           // ray within block
    const int sub     = t >> 3;                  // 0..15
    const int slice   = blockIdx.x & (PSPLIT - 1);
    const int rayBase = (blockIdx.x >> 1) * RPB;

    float cx, cy, cz, C;
    {
        int r = rayBase + rl;
        cx = fmaf(3.0f, rays_d[r * 3 + 0], rays_o[r * 3 + 0]);
        cy = fmaf(3.0f, rays_d[r * 3 + 1], rays_o[r * 3 + 1]);
        cz = fmaf(3.0f, rays_d[r * 3 + 2], rays_o[r * 3 + 2]);
        C  = cx * cx + cy * cy + cz * cz;
    }
    if (t < RPB) sT[t] = 3.0e38f;
    __syncthreads();

    // Per-lane sorted (ascending) top-K in s-domain (s = d^2 - C)
    float best[KSEL];
    int   bidx[KSEL];
#pragma unroll
    for (int j = 0; j < KSEL; j++) { best[j] = 3.0e38f; bidx[j] = 0; }
    float tloc = 3.0e38f;

    const int sliceLo = slice * SLICE;
    const float4* p = g_packed + sliceLo + sub;
    int pbase = sliceLo + sub;

#pragma unroll 1
    for (int c = 0; c < NCHUNK; c++) {
        float Tl = fminf(sTv[rl], tloc);
        float s[UNR];
#pragma unroll
        for (int u = 0; u < UNR; u++) {
            float4 q = p[u * NSUB];
            s[u] = fmaf(cx, q.x, fmaf(cy, q.y, fmaf(cz, q.z, q.w)));
        }
        float m01 = fminf(s[0], s[1]), m23 = fminf(s[2], s[3]);
        float m45 = fminf(s[4], s[5]), m67 = fminf(s[6], s[7]);
        float m = fminf(fminf(m01, m23), fminf(m45, m67));
        if (m < Tl) {
#pragma unroll
            for (int u = 0; u < UNR; u++) {
                if (s[u] < tloc) {
                    float v  = s[u];
                    int   ii = pbase + u * NSUB;
#pragma unroll
                    for (int j = 0; j < KSEL; j++) {
                        if (v < best[j]) {
                            float tv = best[j]; int ti = bidx[j];
                            best[j] = v; bidx[j] = ii;
                            v = tv; ii = ti;
                        }
                    }
                    tloc = best[KSEL - 1];
                }
            }
            if (tloc < sTv[rl]) sTv[rl] = tloc;  // benign race: any stored value is a valid bound
        }
        p     += CHPTS;
        pbase += CHPTS;
    }
    // Tail: 5 points per sub (slice points 49920..49999)
#pragma unroll 1
    for (int k = sliceLo + NCHUNK * CHPTS + sub; k < sliceLo + SLICE; k += NSUB) {
        float4 q = g_packed[k];
        float  s = fmaf(cx, q.x, fmaf(cy, q.y, fmaf(cz, q.z, q.w)));
        if (s < tloc) {
            float v = s; int ii = k;
#pragma unroll
            for (int j = 0; j < KSEL; j++) {
                if (v < best[j]) {
                    float tv = best[j]; int ti = bidx[j];
                    best[j] = v; bidx[j] = ii;
                    v = tv; ii = ti;
                }
            }
            tloc = best[KSEL - 1];
        }
    }

    const int lbase = (rl * NSUB + sub) * KSEL;
#pragma unroll
    for (int j = 0; j < KSEL; j++) {
        md2s[lbase + j]  = best[j] + C;          // back to d^2 domain
        midxs[lbase + j] = bidx[j];
    }

    // Tree merge: 16 sorted lists -> 1 per ray
    for (int stride = NSUB / 2; stride >= 1; stride >>= 1) {
        __syncthreads();
        if (sub < stride) {
            int a = (rl * NSUB + sub) * KSEL;
            int b = (rl * NSUB + sub + stride) * KSEL;
            float ov[KSEL]; int oi[KSEL];
            int ia = 0, ib = 0;
#pragma unroll
            for (int k = 0; k < KSEL; k++) {
                float va = md2s[a + ia], vb = md2s[b + ib];
                if (va <= vb) { ov[k] = va; oi[k] = midxs[a + ia]; ia++; }
                else          { ov[k] = vb; oi[k] = midxs[b + ib]; ib++; }
            }
#pragma unroll
            for (int k = 0; k < KSEL; k++) { md2s[a + k] = ov[k]; midxs[a + k] = oi[k]; }
        }
    }
    __syncthreads();

    if (t < RPB) {
        int src = (t * NSUB) * KSEL;
        int dst = (slice * BATCH + rayBase + t) * KSEL;
#pragma unroll
        for (int k = 0; k < KSEL; k++) {
            g_pd2 [dst + k] = md2s[src + k];
            g_pidx[dst + k] = midxs[src + k];
        }
    }
}

__global__ __launch_bounds__(128)
void finalize_kernel(const float* __restrict__ fdc,
                     const float* __restrict__ opac,
                     float* __restrict__ out)
{
    int ray = blockIdx.x * 128 + threadIdx.x;
    if (ray >= BATCH) return;
    int a = ray * KSEL, b = (BATCH + ray) * KSEL;
    int ia = 0, ib = 0;
    float wsum = 0.f, r0 = 0.f, g0 = 0.f, b0 = 0.f;
#pragma unroll
    for (int k = 0; k < KSEL; k++) {
        float va = (ia < KSEL) ? g_pd2[a + ia] : 3.0e38f;
        float vb = (ib < KSEL) ? g_pd2[b + ib] : 3.0e38f;
        float d2; int ii;
        if (va <= vb) { d2 = va; ii = g_pidx[a + ia]; ia++; }
        else          { d2 = vb; ii = g_pidx[b + ib]; ib++; }
        float d  = sqrtf(fmaxf(d2, 0.0f));
        float op = 1.0f / (1.0f + expf(-opac[ii]));
        float w  = expf(-0.1f * d) * op;
        wsum += w;
        float c0 = 1.0f / (1.0f + expf(-fdc[ii * 3 + 0]));
        float c1 = 1.0f / (1.0f + expf(-fdc[ii * 3 + 1]));
        float c2 = 1.0f / (1.0f + expf(-fdc[ii * 3 + 2]));
        r0 = fmaf(w, c0, r0);
        g0 = fmaf(w, c1, g0);
        b0 = fmaf(w, c2, b0);
    }
    float inv = 1.0f / (wsum + 1e-8f);
    out[ray * 3 + 0] = r0 * inv;
    out[ray * 3 + 1] = g0 * inv;
    out[ray * 3 + 2] = b0 * inv;
}

extern "C" void kernel_launch(void* const* d_in, const int* in_sizes, int n_in,
                              void* d_out, int out_size)
{
    const float* rays_o = (const float*)d_in[0];
    const float* rays_d = (const float*)d_in[1];
    const float* xyz    = (const float*)d_in[2];
    const float* fdc    = (const float*)d_in[3];
    const float* opac   = (const float*)d_in[4];
    float* out = (float*)d_out;

    pack_kernel<<<(NPTS + 255) / 256, 256>>>(xyz);
    scan_kernel<<<GRID, TPB>>>(rays_o, rays_d);
    finalize_kernel<<<BATCH / 128, 128>>>(fdc, opac, out);
}

// round 10
// speedup vs baseline: 2.0932x; 1.0122x over previous
#include <cuda_runtime.h>

#define NPTS   100000
#define BATCH  4096
#define KSEL   10
#define TPB    128
#define RPB    8                        // rays per block (8-way load broadcast)
#define NSUB   (TPB / RPB)              // 16 subs partition the points
#define PSPLIT 2
#define SLICE  (NPTS / PSPLIT)          // 50000
#define GRID   ((BATCH / RPB) * PSPLIT) // 1024 blocks
#define UNR    8
#define CHPTS  (NSUB * UNR)             // 128 points per chunk per block
#define NCHUNK (SLICE / CHPTS)          // 390; tail = 80 points (5 per sub)

__device__ float4 g_packed[NPTS];                  // (-2x, -2y, -2z, |x|^2)
__device__ float  g_pd2 [PSPLIT * BATCH * KSEL];
__device__ int    g_pidx[PSPLIT * BATCH * KSEL];

__global__ __launch_bounds__(256)
void pack_kernel(const float* __restrict__ xyz)
{
    int i = blockIdx.x * 256 + threadIdx.x;
    if (i < NPTS) {
        float x = xyz[i * 3 + 0];
        float y = xyz[i * 3 + 1];
        float z = xyz[i * 3 + 2];
        float q = fmaf(x, x, fmaf(y, y, z * z));
        g_packed[i] = make_float4(-2.0f * x, -2.0f * y, -2.0f * z, q);
    }
}

__global__ __launch_bounds__(TPB, 6)    // 85-reg budget (R9-validated: no spills)
void scan_kernel(const float* __restrict__ rays_o,
                 const float* __restrict__ rays_d)
{
    __shared__ float md2s [RPB * NSUB * KSEL];   // 5 KB
    __shared__ int   midxs[RPB * NSUB * KSEL];   // 5 KB
    __shared__ float sT[RPB];
    volatile float* sTv = sT;

    const int t       = threadIdx.x;
    const int rl      = t & (RPB - 1);           // ray within block
    const int sub     = t >> 3;                  // 0..15
    const int slice   = blockIdx.x & (PSPLIT - 1);
    const int rayBase = (blockIdx.x >> 1) * RPB;

    float cx, cy, cz, C;
    {
        int r = rayBase + rl;
        cx = fmaf(3.0f, rays_d[r * 3 + 0], rays_o[r * 3 + 0]);
        cy = fmaf(3.0f, rays_d[r * 3 + 1], rays_o[r * 3 + 1]);
        cz = fmaf(3.0f, rays_d[r * 3 + 2], rays_o[r * 3 + 2]);
        C  = cx * cx + cy * cy + cz * cz;
    }
    if (t < RPB) sT[t] = 3.0e38f;
    __syncthreads();

    // Per-lane sorted (ascending) top-K in s-domain (s = d^2 - C)
    float best[KSEL];
    int   bidx[KSEL];
#pragma unroll
    for (int j = 0; j < KSEL; j++) { best[j] = 3.0e38f; bidx[j] = 0; }
    float tloc = 3.0e38f;

    const int sliceLo = slice * SLICE;
    const float4* p = g_packed + sliceLo + sub;
    int pbase = sliceLo + sub;

#pragma unroll 1
    for (int c = 0; c < NCHUNK; c++) {
        float Tl = fminf(sTv[rl], tloc);         // tightest known ray-wide bound
        float s[UNR];
#pragma unroll
        for (int u = 0; u < UNR; u++) {
            float4 q = p[u * NSUB];
            s[u] = fmaf(cx, q.x, fmaf(cy, q.y, fmaf(cz, q.z, q.w)));
        }
        float m01 = fminf(s[0], s[1]), m23 = fminf(s[2], s[3]);
        float m45 = fminf(s[4], s[5]), m67 = fminf(s[6], s[7]);
        float m = fminf(fminf(m01, m23), fminf(m45, m67));
        if (m < Tl) {
#pragma unroll
            for (int u = 0; u < UNR; u++) {
                if (s[u] < Tl) {                 // FIX: gate with ray-wide bound, not own tloc
                    float v  = s[u];
                    int   ii = pbase + u * NSUB;
#pragma unroll
                    for (int j = 0; j < KSEL; j++) {
                        if (v < best[j]) {
                            float tv = best[j]; int ti = bidx[j];
                            best[j] = v; bidx[j] = ii;
                            v = tv; ii = ti;
                        }
                    }
                    tloc = best[KSEL - 1];
                    Tl   = fminf(Tl, tloc);      // keep the bound tight within the chunk
                }
            }
            if (tloc < sTv[rl]) sTv[rl] = tloc;  // benign race: any stored value is a valid bound
        }
        p     += CHPTS;
        pbase += CHPTS;
    }
    // Tail: 5 points per sub (slice points 49920..49999)
#pragma unroll 1
    for (int k = sliceLo + NCHUNK * CHPTS + sub; k < sliceLo + SLICE; k += NSUB) {
        float4 q = g_packed[k];
        float  s = fmaf(cx, q.x, fmaf(cy, q.y, fmaf(cz, q.z, q.w)));
        if (s < fminf(sTv[rl], tloc)) {
            float v = s; int ii = k;
#pragma unroll
            for (int j = 0; j < KSEL; j++) {
                if (v < best[j]) {
                    float tv = best[j]; int ti = bidx[j];
                    best[j] = v; bidx[j] = ii;
                    v = tv; ii = ti;
                }
            }
            tloc = best[KSEL - 1];
        }
    }

    const int lbase = (rl * NSUB + sub) * KSEL;
#pragma unroll
    for (int j = 0; j < KSEL; j++) {
        md2s[lbase + j]  = best[j] + C;          // back to d^2 domain
        midxs[lbase + j] = bidx[j];
    }

    // Tree merge: 16 sorted lists -> 1 per ray
    for (int stride = NSUB / 2; stride >= 1; stride >>= 1) {
        __syncthreads();
        if (sub < stride) {
            int a = (rl * NSUB + sub) * KSEL;
            int b = (rl * NSUB + sub + stride) * KSEL;
            float ov[KSEL]; int oi[KSEL];
            int ia = 0, ib = 0;
#pragma unroll
            for (int k = 0; k < KSEL; k++) {
                float va = md2s[a + ia], vb = md2s[b + ib];
                if (va <= vb) { ov[k] = va; oi[k] = midxs[a + ia]; ia++; }
                else          { ov[k] = vb; oi[k] = midxs[b + ib]; ib++; }
            }
#pragma unroll
            for (int k = 0; k < KSEL; k++) { md2s[a + k] = ov[k]; midxs[a + k] = oi[k]; }
        }
    }
    __syncthreads();

    if (t < RPB) {
        int src = (t * NSUB) * KSEL;
        int dst = (slice * BATCH + rayBase + t) * KSEL;
#pragma unroll
        for (int k = 0; k < KSEL; k++) {
            g_pd2 [dst + k] = md2s[src + k];
            g_pidx[dst + k] = midxs[src + k];
        }
    }
}

__global__ __launch_bounds__(128)
void finalize_kernel(const float* __restrict__ fdc,
                     const float* __restrict__ opac,
                     float* __restrict__ out)
{
    int ray = blockIdx.x * 128 + threadIdx.x;
    if (ray >= BATCH) return;
    int a = ray * KSEL, b = (BATCH + ray) * KSEL;
    int ia = 0, ib = 0;
    float wsum = 0.f, r0 = 0.f, g0 = 0.f, b0 = 0.f;
#pragma unroll
    for (int k = 0; k < KSEL; k++) {
        float va = (ia < KSEL) ? g_pd2[a + ia] : 3.0e38f;
        float vb = (ib < KSEL) ? g_pd2[b + ib] : 3.0e38f;
        float d2; int ii;
        if (va <= vb) { d2 = va; ii = g_pidx[a + ia]; ia++; }
        else          { d2 = vb; ii = g_pidx[b + ib]; ib++; }
        float d  = sqrtf(fmaxf(d2, 0.0f));
        float op = 1.0f / (1.0f + expf(-opac[ii]));
        float w  = expf(-0.1f * d) * op;
        wsum += w;
        float c0 = 1.0f / (1.0f + expf(-fdc[ii * 3 + 0]));
        float c1 = 1.0f / (1.0f + expf(-fdc[ii * 3 + 1]));
        float c2 = 1.0f / (1.0f + expf(-fdc[ii * 3 + 2]));
        r0 = fmaf(w, c0, r0);
        g0 = fmaf(w, c1, g0);
        b0 = fmaf(w, c2, b0);
    }
    float inv = 1.0f / (wsum + 1e-8f);
    out[ray * 3 + 0] = r0 * inv;
    out[ray * 3 + 1] = g0 * inv;
    out[ray * 3 + 2] = b0 * inv;
}

extern "C" void kernel_launch(void* const* d_in, const int* in_sizes, int n_in,
                              void* d_out, int out_size)
{
    const float* rays_o = (const float*)d_in[0];
    const float* rays_d = (const float*)d_in[1];
    const float* xyz    = (const float*)d_in[2];
    const float* fdc    = (const float*)d_in[3];
    const float* opac   = (const float*)d_in[4];
    float* out = (float*)d_out;

    pack_kernel<<<(NPTS + 255) / 256, 256>>>(xyz);
    scan_kernel<<<GRID, TPB>>>(rays_o, rays_d);
    finalize_kernel<<<BATCH / 128, 128>>>(fdc, opac, out);
}